// round 16
// baseline (speedup 1.0000x reference)
#include <cuda_runtime.h>

typedef unsigned long long u64;

// ---------------- device scratch ----------------
__device__ float g_Bmat[128 * 1024];     // [k'][ij]
__device__ float g_Cc[1024];             // C[ij]
__device__ float g_KG[1024 * 128];       // [ij][c]
__device__ float g_W[1024 * 1024];       // weights
__device__ float g_part[8 * 1024 * 128]; // GEMM2 k-split partials (split 8)
__device__ float g_denp[16 * 1024];      // den partials per gemm1 n-block (16)

// ---------------- packed f32x2 helpers ----------------
__device__ __forceinline__ u64 pack2(float lo, float hi) {
    u64 r; asm("mov.b64 %0,{%1,%2};" : "=l"(r) : "f"(lo), "f"(hi)); return r;
}
__device__ __forceinline__ void unpack2(u64 v, float& lo, float& hi) {
    asm("mov.b64 {%0,%1},%2;" : "=f"(lo), "=f"(hi) : "l"(v));
}
__device__ __forceinline__ void fma2(u64& c, u64 a, u64 b) {
    asm("fma.rn.f32x2 %0,%1,%2,%0;" : "+l"(c) : "l"(a), "l"(b));
}

// ---------------- kernel 1: precompute (exact R6) ----------------
__global__ __launch_bounds__(1024) void precompute_ij(const float* __restrict__ Mu0,
                                                      const float* __restrict__ Mu1,
                                                      const float* __restrict__ S0,
                                                      const float* __restrict__ S1,
                                                      const float* __restrict__ tptr) {
    __shared__ float bm[128][33];
    const int tid = threadIdx.x;
    const int w = tid >> 5, lane = tid & 31;
    const int ij0 = blockIdx.x * 32;
    const int ij = ij0 + w;
    const int i = ij >> 5, j = ij & 31;
    const float t = *tptr, u = 1.0f - t;

    float Csum = 0.0f;
    #pragma unroll
    for (int kk = 0; kk < 2; kk++) {
        int k = kk * 32 + lane;
        float s0 = S0[i * 64 + k], s1 = S1[j * 64 + k];
        float m0 = Mu0[i * 64 + k], m1 = Mu1[j * 64 + k];
        float Ds = sqrtf(4.0f * s0 * s1 + 0.0625f);
        float Cs = 0.5f * (Ds - 0.25f);
        float mu = u * m0 + t * m1;
        float Sig = u * u * s0 + t * t * s1 + 2.0f * t * u * (Cs + 0.125f);
        float St = t * s1 + u * Cs - (u * s0 + t * Cs) - 0.25f * t;
        float invS = 1.0f / Sig;
        float Kv = St * invS;
        float v = m1 - m0;
        bm[k][w] = invS;
        bm[64 + k][w] = -2.0f * mu * invS;
        g_KG[ij * 128 + k] = Kv;
        g_KG[ij * 128 + 64 + k] = v - Kv * mu;
        Csum += mu * mu * invS + __logf(Sig);
    }
    #pragma unroll
    for (int o = 16; o > 0; o >>= 1) Csum += __shfl_xor_sync(0xffffffffu, Csum, o);
    if (lane == 0) g_Cc[ij] = Csum;
    __syncthreads();

    const int r = tid >> 3, c = (tid & 7) * 4;
    float4 v4 = make_float4(bm[r][c], bm[r][c + 1], bm[r][c + 2], bm[r][c + 3]);
    *(float4*)&g_Bmat[r * 1024 + ij0 + c] = v4;
}

// ================= GEMM geometry: BM=64, BN=64, BK=16, 256 threads =================
// Thread tile 4m x 4n; acc packed along N (4 m x 2 n-pairs).
// A pre-duplicated in smem as u64 {a,a}; B read from smem as adjacent-pair u64.
// Inner kstep: 3 LDS.128 + 8 FMA2 = 11 instrs (R6 had 18).

// ---------------- GEMM1: q = Xext @ Bmat, W epilogue ----------------
__global__ __launch_bounds__(256) void gemm1_kernel(const float* __restrict__ X,
                                                    const float* __restrict__ Lam) {
    __shared__ u64   As[2][16][64];   // 16 KB (duplicated {a,a})
    __shared__ float Bs[2][16][64];   // 8 KB

    const int tid = threadIdx.x;
    const int tx = tid & 15, ty = tid >> 4;
    const int m0 = blockIdx.x * 64, n0 = blockIdx.y * 64;

    const int rA = tid & 63, sA = tid >> 6;
    const int rB = tid >> 4, cB = (tid & 15) * 4;

    u64 acc[4][2];
    #pragma unroll
    for (int i = 0; i < 4; i++) { acc[i][0] = 0ULL; acc[i][1] = 0ULL; }

    // stage chunk 0 (X cols 0..15, squared)
    {
        float4 v = *(const float4*)&X[(m0 + rA) * 64 + sA * 4];
        v.x *= v.x; v.y *= v.y; v.z *= v.z; v.w *= v.w;
        As[0][sA * 4 + 0][rA] = pack2(v.x, v.x);
        As[0][sA * 4 + 1][rA] = pack2(v.y, v.y);
        As[0][sA * 4 + 2][rA] = pack2(v.z, v.z);
        As[0][sA * 4 + 3][rA] = pack2(v.w, v.w);
        *(float4*)&Bs[0][rB][cB] = *(const float4*)&g_Bmat[rB * 1024 + n0 + cB];
    }
    __syncthreads();

    #pragma unroll 1
    for (int c = 0; c < 8; c++) {
        const int p = c & 1;
        float4 va, vb;
        if (c < 7) {
            int cc = c + 1;
            va = *(const float4*)&X[(m0 + rA) * 64 + (cc & 3) * 16 + sA * 4];
            if (cc < 4) { va.x *= va.x; va.y *= va.y; va.z *= va.z; va.w *= va.w; }
            vb = *(const float4*)&g_Bmat[(cc * 16 + rB) * 1024 + n0 + cB];
        }
        #pragma unroll
        for (int k = 0; k < 16; k++) {
            ulonglong2 a01 = *(const ulonglong2*)&As[p][k][ty * 4];
            ulonglong2 a23 = *(const ulonglong2*)&As[p][k][ty * 4 + 2];
            ulonglong2 b   = *(const ulonglong2*)&Bs[p][k][tx * 4];  // {b0,b1},{b2,b3}
            fma2(acc[0][0], a01.x, b.x); fma2(acc[0][1], a01.x, b.y);
            fma2(acc[1][0], a01.y, b.x); fma2(acc[1][1], a01.y, b.y);
            fma2(acc[2][0], a23.x, b.x); fma2(acc[2][1], a23.x, b.y);
            fma2(acc[3][0], a23.y, b.x); fma2(acc[3][1], a23.y, b.y);
        }
        if (c < 7) {
            As[p ^ 1][sA * 4 + 0][rA] = pack2(va.x, va.x);
            As[p ^ 1][sA * 4 + 1][rA] = pack2(va.y, va.y);
            As[p ^ 1][sA * 4 + 2][rA] = pack2(va.z, va.z);
            As[p ^ 1][sA * 4 + 3][rA] = pack2(va.w, va.w);
            *(float4*)&Bs[p ^ 1][rB][cB] = vb;
            __syncthreads();
        }
    }

    // ---- epilogue: W + den partials (acc now n-packed: rows individually) ----
    float4 cc4 = *(const float4*)&g_Cc[n0 + tx * 4];
    float4 ll4 = *(const float4*)&Lam[n0 + tx * 4];
    float ccs[4] = {cc4.x, cc4.y, cc4.z, cc4.w};
    float lls[4] = {ll4.x, ll4.y, ll4.z, ll4.w};

    #pragma unroll
    for (int i = 0; i < 4; i++) {
        float w0, w1, w2, w3;
        unpack2(acc[i][0], w0, w1);
        unpack2(acc[i][1], w2, w3);
        w0 = __expf(fminf(fmaxf(-0.5f * (w0 + ccs[0]), -50.0f), 50.0f)) * lls[0];
        w1 = __expf(fminf(fmaxf(-0.5f * (w1 + ccs[1]), -50.0f), 50.0f)) * lls[1];
        w2 = __expf(fminf(fmaxf(-0.5f * (w2 + ccs[2]), -50.0f), 50.0f)) * lls[2];
        w3 = __expf(fminf(fmaxf(-0.5f * (w3 + ccs[3]), -50.0f), 50.0f)) * lls[3];
        int m = m0 + ty * 4 + i;
        *(float4*)&g_W[m * 1024 + n0 + tx * 4] = make_float4(w0, w1, w2, w3);
        float rsum = (w0 + w1) + (w2 + w3);
        #pragma unroll
        for (int o = 1; o < 16; o <<= 1) rsum += __shfl_xor_sync(0xffffffffu, rsum, o);
        if (tx == 0) g_denp[blockIdx.y * 1024 + m] = rsum;
    }
}

// ---------------- GEMM2: part = W @ KG, split 8 ----------------
__global__ __launch_bounds__(256) void gemm2_kernel() {
    __shared__ u64   As[2][16][64];
    __shared__ float Bs[2][16][64];

    const int tid = threadIdx.x;
    const int tx = tid & 15, ty = tid >> 4;
    const int m0 = blockIdx.x * 64, n0 = blockIdx.y * 64;
    const int k0 = blockIdx.z * 128;

    const int rA = tid & 63, sA = tid >> 6;
    const int rB = tid >> 4, cB = (tid & 15) * 4;

    u64 acc[4][2];
    #pragma unroll
    for (int i = 0; i < 4; i++) { acc[i][0] = 0ULL; acc[i][1] = 0ULL; }

    {
        float4 v = *(const float4*)&g_W[(m0 + rA) * 1024 + k0 + sA * 4];
        As[0][sA * 4 + 0][rA] = pack2(v.x, v.x);
        As[0][sA * 4 + 1][rA] = pack2(v.y, v.y);
        As[0][sA * 4 + 2][rA] = pack2(v.z, v.z);
        As[0][sA * 4 + 3][rA] = pack2(v.w, v.w);
        *(float4*)&Bs[0][rB][cB] = *(const float4*)&g_KG[(k0 + rB) * 128 + n0 + cB];
    }
    __syncthreads();

    #pragma unroll 1
    for (int c = 0; c < 8; c++) {
        const int p = c & 1;
        float4 va, vb;
        if (c < 7) {
            int cc = c + 1;
            va = *(const float4*)&g_W[(m0 + rA) * 1024 + k0 + cc * 16 + sA * 4];
            vb = *(const float4*)&g_KG[(k0 + cc * 16 + rB) * 128 + n0 + cB];
        }
        #pragma unroll
        for (int k = 0; k < 16; k++) {
            ulonglong2 a01 = *(const ulonglong2*)&As[p][k][ty * 4];
            ulonglong2 a23 = *(const ulonglong2*)&As[p][k][ty * 4 + 2];
            ulonglong2 b   = *(const ulonglong2*)&Bs[p][k][tx * 4];
            fma2(acc[0][0], a01.x, b.x); fma2(acc[0][1], a01.x, b.y);
            fma2(acc[1][0], a01.y, b.x); fma2(acc[1][1], a01.y, b.y);
            fma2(acc[2][0], a23.x, b.x); fma2(acc[2][1], a23.x, b.y);
            fma2(acc[3][0], a23.y, b.x); fma2(acc[3][1], a23.y, b.y);
        }
        if (c < 7) {
            As[p ^ 1][sA * 4 + 0][rA] = pack2(va.x, va.x);
            As[p ^ 1][sA * 4 + 1][rA] = pack2(va.y, va.y);
            As[p ^ 1][sA * 4 + 2][rA] = pack2(va.z, va.z);
            As[p ^ 1][sA * 4 + 3][rA] = pack2(va.w, va.w);
            *(float4*)&Bs[p ^ 1][rB][cB] = vb;
            __syncthreads();
        }
    }

    const int s = blockIdx.z;
    #pragma unroll
    for (int i = 0; i < 4; i++) {
        float v0, v1, v2, v3;
        unpack2(acc[i][0], v0, v1);
        unpack2(acc[i][1], v2, v3);
        int m = m0 + ty * 4 + i;
        *(float4*)&g_part[(s * 1024 + m) * 128 + n0 + tx * 4] = make_float4(v0, v1, v2, v3);
    }
}

// ---------------- final: warp per batch row, split 8 (exact R6) ----------------
__global__ __launch_bounds__(128) void final_kernel(const float* __restrict__ X,
                                                    float* __restrict__ out) {
    const int tid = threadIdx.x;
    const int b = blockIdx.x * 4 + (tid >> 5);
    const int lane = tid & 31;
    const int l = lane & 15;
    const int h = lane >> 4;
    const int k4 = l * 4;

    float4 A = make_float4(0.f, 0.f, 0.f, 0.f);
    float4 Bv = make_float4(0.f, 0.f, 0.f, 0.f);
    #pragma unroll
    for (int si = 0; si < 4; si++) {
        int s = h * 4 + si;
        float4 a = *(const float4*)&g_part[(s * 1024 + b) * 128 + k4];
        float4 q = *(const float4*)&g_part[(s * 1024 + b) * 128 + 64 + k4];
        A.x += a.x; A.y += a.y; A.z += a.z; A.w += a.w;
        Bv.x += q.x; Bv.y += q.y; Bv.z += q.z; Bv.w += q.w;
    }
    A.x += __shfl_xor_sync(0xffffffffu, A.x, 16);
    A.y += __shfl_xor_sync(0xffffffffu, A.y, 16);
    A.z += __shfl_xor_sync(0xffffffffu, A.z, 16);
    A.w += __shfl_xor_sync(0xffffffffu, A.w, 16);
    Bv.x += __shfl_xor_sync(0xffffffffu, Bv.x, 16);
    Bv.y += __shfl_xor_sync(0xffffffffu, Bv.y, 16);
    Bv.z += __shfl_xor_sync(0xffffffffu, Bv.z, 16);
    Bv.w += __shfl_xor_sync(0xffffffffu, Bv.w, 16);

    float d = g_denp[l * 1024 + b];
    #pragma unroll
    for (int o = 1; o < 16; o <<= 1) d += __shfl_xor_sync(0xffffffffu, d, o);
    float inv = 1.0f / d;

    if (h == 0) {
        float4 x = *(const float4*)&X[b * 64 + k4];
        float4 o4;
        o4.x = (x.x * A.x + Bv.x) * inv;
        o4.y = (x.y * A.y + Bv.y) * inv;
        o4.z = (x.z * A.z + Bv.z) * inv;
        o4.w = (x.w * A.w + Bv.w) * inv;
        *(float4*)&out[b * 64 + k4] = o4;
    }
}

// ---------------- launch (R6 grids) ----------------
extern "C" void kernel_launch(void* const* d_in, const int* in_sizes, int n_in,
                              void* d_out, int out_size) {
    const float* X   = (const float*)d_in[0];
    const float* Mu0 = (const float*)d_in[1];
    const float* Mu1 = (const float*)d_in[2];
    const float* S0  = (const float*)d_in[3];
    const float* S1  = (const float*)d_in[4];
    const float* Lam = (const float*)d_in[5];
    const float* t   = (const float*)d_in[6];
    float* out = (float*)d_out;

    precompute_ij<<<32, 1024>>>(Mu0, Mu1, S0, S1, t);
    gemm1_kernel<<<dim3(16, 16), 256>>>(X, Lam);
    gemm2_kernel<<<dim3(16, 2, 8), 256>>>();
    final_kernel<<<256, 128>>>(X, out);
}

// round 17
// speedup vs baseline: 1.2898x; 1.2898x over previous
#include <cuda_runtime.h>

typedef unsigned long long u64;

// ---------------- device scratch ----------------
__device__ float g_Bmat[128 * 1024];     // [k'][ij]
__device__ float g_Cc[1024];             // C[ij]
__device__ float g_KG[1024 * 128];       // [ij][c]
__device__ float g_W[1024 * 1024];       // weights
__device__ float g_part[8 * 1024 * 128]; // GEMM2 k-split partials (split 8)
__device__ float g_denp[16 * 1024];      // den partials per gemm1 n-block (16)

// ---------------- packed f32x2 helpers ----------------
__device__ __forceinline__ u64 pack2(float lo, float hi) {
    u64 r; asm("mov.b64 %0,{%1,%2};" : "=l"(r) : "f"(lo), "f"(hi)); return r;
}
__device__ __forceinline__ void unpack2(u64 v, float& lo, float& hi) {
    asm("mov.b64 {%0,%1},%2;" : "=f"(lo), "=f"(hi) : "l"(v));
}
__device__ __forceinline__ void fma2(u64& c, u64 a, u64 b) {
    asm("fma.rn.f32x2 %0,%1,%2,%0;" : "+l"(c) : "l"(a), "l"(b));
}

// ---------------- kernel 1: precompute (exact R6) ----------------
__global__ __launch_bounds__(1024) void precompute_ij(const float* __restrict__ Mu0,
                                                      const float* __restrict__ Mu1,
                                                      const float* __restrict__ S0,
                                                      const float* __restrict__ S1,
                                                      const float* __restrict__ tptr) {
    __shared__ float bm[128][33];
    const int tid = threadIdx.x;
    const int w = tid >> 5, lane = tid & 31;
    const int ij0 = blockIdx.x * 32;
    const int ij = ij0 + w;
    const int i = ij >> 5, j = ij & 31;
    const float t = *tptr, u = 1.0f - t;

    float Csum = 0.0f;
    #pragma unroll
    for (int kk = 0; kk < 2; kk++) {
        int k = kk * 32 + lane;
        float s0 = S0[i * 64 + k], s1 = S1[j * 64 + k];
        float m0 = Mu0[i * 64 + k], m1 = Mu1[j * 64 + k];
        float Ds = sqrtf(4.0f * s0 * s1 + 0.0625f);
        float Cs = 0.5f * (Ds - 0.25f);
        float mu = u * m0 + t * m1;
        float Sig = u * u * s0 + t * t * s1 + 2.0f * t * u * (Cs + 0.125f);
        float St = t * s1 + u * Cs - (u * s0 + t * Cs) - 0.25f * t;
        float invS = 1.0f / Sig;
        float Kv = St * invS;
        float v = m1 - m0;
        bm[k][w] = invS;
        bm[64 + k][w] = -2.0f * mu * invS;
        g_KG[ij * 128 + k] = Kv;
        g_KG[ij * 128 + 64 + k] = v - Kv * mu;
        Csum += mu * mu * invS + __logf(Sig);
    }
    #pragma unroll
    for (int o = 16; o > 0; o >>= 1) Csum += __shfl_xor_sync(0xffffffffu, Csum, o);
    if (lane == 0) g_Cc[ij] = Csum;
    __syncthreads();

    const int r = tid >> 3, c = (tid & 7) * 4;
    float4 v4 = make_float4(bm[r][c], bm[r][c + 1], bm[r][c + 2], bm[r][c + 3]);
    *(float4*)&g_Bmat[r * 1024 + ij0 + c] = v4;
}

// ================= GEMM geometry: BM=128, BN=64, BK=16, 256 threads =================
// Thread tile 8m x 4n (acc f32x2 packed along m: 4 m-pairs x 4 n).
// Per kstep: 3 LDS.128 + 4 pack + 16 FMA2 -> half the smem bytes per FMA2 of R6.

// ---------------- GEMM1: q = Xext @ Bmat, W epilogue ----------------
__global__ __launch_bounds__(256) void gemm1_kernel(const float* __restrict__ X,
                                                    const float* __restrict__ Lam) {
    __shared__ float As[2][16][128];  // 16 KB
    __shared__ float Bs[2][16][64];   // 8 KB

    const int tid = threadIdx.x;
    const int tx = tid & 15, ty = tid >> 4;        // 16 x 16; thread: 8m x 4n
    const int m0 = blockIdx.x * 128, n0 = blockIdx.y * 64;

    const int rA = tid & 127, sA = tid >> 7;       // A stage: m-row, k-half (0..1)
    const int rB = tid >> 4, cB = (tid & 15) * 4;  // B stage

    u64 acc[4][4];
    #pragma unroll
    for (int i = 0; i < 4; i++)
        #pragma unroll
        for (int j = 0; j < 4; j++) acc[i][j] = 0ULL;

    // stage chunk 0 (X cols 0..15, squared)
    {
        #pragma unroll
        for (int h = 0; h < 2; h++) {
            float4 v = *(const float4*)&X[(m0 + rA) * 64 + sA * 8 + h * 4];
            v.x *= v.x; v.y *= v.y; v.z *= v.z; v.w *= v.w;
            As[0][sA * 8 + h * 4 + 0][rA] = v.x; As[0][sA * 8 + h * 4 + 1][rA] = v.y;
            As[0][sA * 8 + h * 4 + 2][rA] = v.z; As[0][sA * 8 + h * 4 + 3][rA] = v.w;
        }
        *(float4*)&Bs[0][rB][cB] = *(const float4*)&g_Bmat[rB * 1024 + n0 + cB];
    }
    __syncthreads();

    #pragma unroll 1
    for (int c = 0; c < 8; c++) {
        const int p = c & 1;
        float4 va0, va1, vb;
        if (c < 7) {
            int cc = c + 1;
            int colb = (cc & 3) * 16 + sA * 8;
            va0 = *(const float4*)&X[(m0 + rA) * 64 + colb];
            va1 = *(const float4*)&X[(m0 + rA) * 64 + colb + 4];
            if (cc < 4) {
                va0.x *= va0.x; va0.y *= va0.y; va0.z *= va0.z; va0.w *= va0.w;
                va1.x *= va1.x; va1.y *= va1.y; va1.z *= va1.z; va1.w *= va1.w;
            }
            vb = *(const float4*)&g_Bmat[(cc * 16 + rB) * 1024 + n0 + cB];
        }
        #pragma unroll
        for (int k = 0; k < 16; k++) {
            ulonglong2 a01 = *(const ulonglong2*)&As[p][k][ty * 8];
            ulonglong2 a23 = *(const ulonglong2*)&As[p][k][ty * 8 + 4];
            float4 b = *(const float4*)&Bs[p][k][tx * 4];
            u64 b0 = pack2(b.x, b.x), b1 = pack2(b.y, b.y);
            u64 b2 = pack2(b.z, b.z), b3 = pack2(b.w, b.w);
            fma2(acc[0][0], a01.x, b0); fma2(acc[0][1], a01.x, b1);
            fma2(acc[0][2], a01.x, b2); fma2(acc[0][3], a01.x, b3);
            fma2(acc[1][0], a01.y, b0); fma2(acc[1][1], a01.y, b1);
            fma2(acc[1][2], a01.y, b2); fma2(acc[1][3], a01.y, b3);
            fma2(acc[2][0], a23.x, b0); fma2(acc[2][1], a23.x, b1);
            fma2(acc[2][2], a23.x, b2); fma2(acc[2][3], a23.x, b3);
            fma2(acc[3][0], a23.y, b0); fma2(acc[3][1], a23.y, b1);
            fma2(acc[3][2], a23.y, b2); fma2(acc[3][3], a23.y, b3);
        }
        if (c < 7) {
            As[p ^ 1][sA * 8 + 0][rA] = va0.x; As[p ^ 1][sA * 8 + 1][rA] = va0.y;
            As[p ^ 1][sA * 8 + 2][rA] = va0.z; As[p ^ 1][sA * 8 + 3][rA] = va0.w;
            As[p ^ 1][sA * 8 + 4][rA] = va1.x; As[p ^ 1][sA * 8 + 5][rA] = va1.y;
            As[p ^ 1][sA * 8 + 6][rA] = va1.z; As[p ^ 1][sA * 8 + 7][rA] = va1.w;
            *(float4*)&Bs[p ^ 1][rB][cB] = vb;
            __syncthreads();
        }
    }

    // ---- epilogue: W + den partials (4 m-pairs) ----
    float4 cc4 = *(const float4*)&g_Cc[n0 + tx * 4];
    float4 ll4 = *(const float4*)&Lam[n0 + tx * 4];
    float ccs[4] = {cc4.x, cc4.y, cc4.z, cc4.w};
    float lls[4] = {ll4.x, ll4.y, ll4.z, ll4.w};

    #pragma unroll
    for (int mp = 0; mp < 4; mp++) {
        float wlo[4], whi[4];
        #pragma unroll
        for (int j = 0; j < 4; j++) {
            float qlo, qhi;
            unpack2(acc[mp][j], qlo, qhi);
            wlo[j] = __expf(fminf(fmaxf(-0.5f * (qlo + ccs[j]), -50.0f), 50.0f)) * lls[j];
            whi[j] = __expf(fminf(fmaxf(-0.5f * (qhi + ccs[j]), -50.0f), 50.0f)) * lls[j];
        }
        int mlo = m0 + ty * 8 + 2 * mp;
        *(float4*)&g_W[mlo * 1024 + n0 + tx * 4]       = *(float4*)&wlo[0];
        *(float4*)&g_W[(mlo + 1) * 1024 + n0 + tx * 4] = *(float4*)&whi[0];
        float rlo = (wlo[0] + wlo[1]) + (wlo[2] + wlo[3]);
        float rhi = (whi[0] + whi[1]) + (whi[2] + whi[3]);
        #pragma unroll
        for (int o = 1; o < 16; o <<= 1) {
            rlo += __shfl_xor_sync(0xffffffffu, rlo, o);
            rhi += __shfl_xor_sync(0xffffffffu, rhi, o);
        }
        if (tx == 0) {
            g_denp[blockIdx.y * 1024 + mlo]     = rlo;
            g_denp[blockIdx.y * 1024 + mlo + 1] = rhi;
        }
    }
}

// ---------------- GEMM2: part = W @ KG, split 8, BM=128, BN=64 ----------------
__global__ __launch_bounds__(256) void gemm2_kernel() {
    __shared__ float As[2][16][128];
    __shared__ float Bs[2][16][64];

    const int tid = threadIdx.x;
    const int tx = tid & 15, ty = tid >> 4;
    const int m0 = blockIdx.x * 128, n0 = blockIdx.y * 64;
    const int k0 = blockIdx.z * 128;

    const int rA = tid & 127, sA = tid >> 7;
    const int rB = tid >> 4, cB = (tid & 15) * 4;

    u64 acc[4][4];
    #pragma unroll
    for (int i = 0; i < 4; i++)
        #pragma unroll
        for (int j = 0; j < 4; j++) acc[i][j] = 0ULL;

    {
        #pragma unroll
        for (int h = 0; h < 2; h++) {
            float4 v = *(const float4*)&g_W[(m0 + rA) * 1024 + k0 + sA * 8 + h * 4];
            As[0][sA * 8 + h * 4 + 0][rA] = v.x; As[0][sA * 8 + h * 4 + 1][rA] = v.y;
            As[0][sA * 8 + h * 4 + 2][rA] = v.z; As[0][sA * 8 + h * 4 + 3][rA] = v.w;
        }
        *(float4*)&Bs[0][rB][cB] = *(const float4*)&g_KG[(k0 + rB) * 128 + n0 + cB];
    }
    __syncthreads();

    #pragma unroll 1
    for (int c = 0; c < 8; c++) {
        const int p = c & 1;
        float4 va0, va1, vb;
        if (c < 7) {
            int kb = k0 + (c + 1) * 16 + sA * 8;
            va0 = *(const float4*)&g_W[(m0 + rA) * 1024 + kb];
            va1 = *(const float4*)&g_W[(m0 + rA) * 1024 + kb + 4];
            vb = *(const float4*)&g_KG[(k0 + (c + 1) * 16 + rB) * 128 + n0 + cB];
        }
        #pragma unroll
        for (int k = 0; k < 16; k++) {
            ulonglong2 a01 = *(const ulonglong2*)&As[p][k][ty * 8];
            ulonglong2 a23 = *(const ulonglong2*)&As[p][k][ty * 8 + 4];
            float4 b = *(const float4*)&Bs[p][k][tx * 4];
            u64 b0 = pack2(b.x, b.x), b1 = pack2(b.y, b.y);
            u64 b2 = pack2(b.z, b.z), b3 = pack2(b.w, b.w);
            fma2(acc[0][0], a01.x, b0); fma2(acc[0][1], a01.x, b1);
            fma2(acc[0][2], a01.x, b2); fma2(acc[0][3], a01.x, b3);
            fma2(acc[1][0], a01.y, b0); fma2(acc[1][1], a01.y, b1);
            fma2(acc[1][2], a01.y, b2); fma2(acc[1][3], a01.y, b3);
            fma2(acc[2][0], a23.x, b0); fma2(acc[2][1], a23.x, b1);
            fma2(acc[2][2], a23.x, b2); fma2(acc[2][3], a23.x, b3);
            fma2(acc[3][0], a23.y, b0); fma2(acc[3][1], a23.y, b1);
            fma2(acc[3][2], a23.y, b2); fma2(acc[3][3], a23.y, b3);
        }
        if (c < 7) {
            As[p ^ 1][sA * 8 + 0][rA] = va0.x; As[p ^ 1][sA * 8 + 1][rA] = va0.y;
            As[p ^ 1][sA * 8 + 2][rA] = va0.z; As[p ^ 1][sA * 8 + 3][rA] = va0.w;
            As[p ^ 1][sA * 8 + 4][rA] = va1.x; As[p ^ 1][sA * 8 + 5][rA] = va1.y;
            As[p ^ 1][sA * 8 + 6][rA] = va1.z; As[p ^ 1][sA * 8 + 7][rA] = va1.w;
            *(float4*)&Bs[p ^ 1][rB][cB] = vb;
            __syncthreads();
        }
    }

    const int s = blockIdx.z;
    #pragma unroll
    for (int mp = 0; mp < 4; mp++) {
        float vlo[4], vhi[4];
        #pragma unroll
        for (int j = 0; j < 4; j++) unpack2(acc[mp][j], vlo[j], vhi[j]);
        int mlo = m0 + ty * 8 + 2 * mp;
        *(float4*)&g_part[(s * 1024 + mlo) * 128 + n0 + tx * 4]     = *(float4*)&vlo[0];
        *(float4*)&g_part[(s * 1024 + mlo + 1) * 128 + n0 + tx * 4] = *(float4*)&vhi[0];
    }
}

// ---------------- final: warp per batch row, split 8 (exact R6) ----------------
__global__ __launch_bounds__(128) void final_kernel(const float* __restrict__ X,
                                                    float* __restrict__ out) {
    const int tid = threadIdx.x;
    const int b = blockIdx.x * 4 + (tid >> 5);
    const int lane = tid & 31;
    const int l = lane & 15;
    const int h = lane >> 4;
    const int k4 = l * 4;

    float4 A = make_float4(0.f, 0.f, 0.f, 0.f);
    float4 Bv = make_float4(0.f, 0.f, 0.f, 0.f);
    #pragma unroll
    for (int si = 0; si < 4; si++) {
        int s = h * 4 + si;
        float4 a = *(const float4*)&g_part[(s * 1024 + b) * 128 + k4];
        float4 q = *(const float4*)&g_part[(s * 1024 + b) * 128 + 64 + k4];
        A.x += a.x; A.y += a.y; A.z += a.z; A.w += a.w;
        Bv.x += q.x; Bv.y += q.y; Bv.z += q.z; Bv.w += q.w;
    }
    A.x += __shfl_xor_sync(0xffffffffu, A.x, 16);
    A.y += __shfl_xor_sync(0xffffffffu, A.y, 16);
    A.z += __shfl_xor_sync(0xffffffffu, A.z, 16);
    A.w += __shfl_xor_sync(0xffffffffu, A.w, 16);
    Bv.x += __shfl_xor_sync(0xffffffffu, Bv.x, 16);
    Bv.y += __shfl_xor_sync(0xffffffffu, Bv.y, 16);
    Bv.z += __shfl_xor_sync(0xffffffffu, Bv.z, 16);
    Bv.w += __shfl_xor_sync(0xffffffffu, Bv.w, 16);

    float d = g_denp[l * 1024 + b];
    #pragma unroll
    for (int o = 1; o < 16; o <<= 1) d += __shfl_xor_sync(0xffffffffu, d, o);
    float inv = 1.0f / d;

    if (h == 0) {
        float4 x = *(const float4*)&X[b * 64 + k4];
        float4 o4;
        o4.x = (x.x * A.x + Bv.x) * inv;
        o4.y = (x.y * A.y + Bv.y) * inv;
        o4.z = (x.z * A.z + Bv.z) * inv;
        o4.w = (x.w * A.w + Bv.w) * inv;
        *(float4*)&out[b * 64 + k4] = o4;
    }
}

// ---------------- launch ----------------
extern "C" void kernel_launch(void* const* d_in, const int* in_sizes, int n_in,
                              void* d_out, int out_size) {
    const float* X   = (const float*)d_in[0];
    const float* Mu0 = (const float*)d_in[1];
    const float* Mu1 = (const float*)d_in[2];
    const float* S0  = (const float*)d_in[3];
    const float* S1  = (const float*)d_in[4];
    const float* Lam = (const float*)d_in[5];
    const float* t   = (const float*)d_in[6];
    float* out = (float*)d_out;

    precompute_ij<<<32, 1024>>>(Mu0, Mu1, S0, S1, t);
    gemm1_kernel<<<dim3(8, 16), 256>>>(X, Lam);
    gemm2_kernel<<<dim3(8, 2, 8), 256>>>();
    final_kernel<<<256, 128>>>(X, out);
}